// round 13
// baseline (speedup 1.0000x reference)
#include <cuda_runtime.h>
#include <cuda_bf16.h>
#include <cuda_fp16.h>

#define Vv 32000
#define Ee 128
#define Bb 32
#define Tt 128
#define Gg 512
#define Ll 2

// ---- fp32 device-global copies (NEVER passed as kernel args from host) ----
__device__ float g_emb[Vv * Ee];
__device__ float g_swT[Ee * Vv];        // softmax_w transposed [k][v]
__device__ float g_wx [Ll * Ee * Gg];
__device__ float g_wh [Ll * Ee * Gg];
__device__ float g_al [Ll * Gg];
__device__ float g_b1 [Ll * Gg];
__device__ float g_b2 [Ll * Gg];
__device__ float g_bi [Ll * Gg];
__device__ float g_wi [Ll * Ee];
__device__ float g_wf [Ll * Ee];
__device__ float g_wo [Ll * Ee];
__device__ float g_sb [Vv];
// ---- scratch ----
__device__ float g_xh [Tt * Bb * Gg];
__device__ float g_h0 [Tt * Bb * Ee];
__device__ float g_h1 [Bb * Tt * Ee];
__device__ float g_whT[Ll * Gg * Ee];
__device__ int   g_dt;
__device__ int   g_flag;

__device__ __forceinline__ float sigf(float x) { return 1.0f / (1.0f + __expf(-x)); }

__global__ void k_reset() { g_flag = 0; }

__global__ void k_probe(const unsigned* __restrict__ w) {   // alpha == ones
    unsigned v = w[0];
    int dt = 0;
    if (v == 0x3F803F80u) dt = 1;        // bf16
    else if (v == 0x3C003C00u) dt = 2;   // f16
    g_dt = dt;
}

__device__ __forceinline__ float load_as_f32(const void* src, long i, int dt) {
    if (dt == 1) return __bfloat162float(((const __nv_bfloat16*)src)[i]);
    if (dt == 2) return __half2float(((const __half*)src)[i]);
    return ((const float*)src)[i];
}

// Destination chosen INSIDE device code (symbol-arg bug fix).
__global__ void k_conv_sel(const void* __restrict__ src, long n, int which) {
    const int dt = g_dt;
    float* dst;
    switch (which) {
        case 0:  dst = g_emb; break;
        case 1:  dst = g_wx;  break;
        case 2:  dst = g_wh;  break;
        case 3:  dst = g_al;  break;
        case 4:  dst = g_b1;  break;
        case 5:  dst = g_b2;  break;
        case 6:  dst = g_bi;  break;
        case 7:  dst = g_wi;  break;
        case 8:  dst = g_wf;  break;
        case 9:  dst = g_wo;  break;
        default: dst = g_sb;  break;
    }
    long i0 = (long)blockIdx.x * blockDim.x + threadIdx.x;
    long st = (long)gridDim.x * blockDim.x;
    for (long i = i0; i < n; i += st) dst[i] = load_as_f32(src, i, dt);
}

// softmax_w (V,E) -> g_swT (E,V), conversion fused
__global__ void k_swT(const void* __restrict__ sw) {
    const int dt = g_dt;
    long i0 = (long)blockIdx.x * blockDim.x + threadIdx.x;
    long st = (long)gridDim.x * blockDim.x;
    const long n = (long)Ee * Vv;
    for (long i = i0; i < n; i += st) {
        long k = i / Vv, v = i - k * Vv;
        g_swT[i] = load_as_f32(sw, v * Ee + k, dt);
    }
}

__global__ void k_transpose_wh() {
    int bl = blockIdx.x;                 // l*512 + j
    int l = bl >> 9, j = bl & 511;
    int k = threadIdx.x;
    g_whT[bl * Ee + k] = g_wh[l * Ee * Gg + k * Gg + j];
}

// XH[r][j] = dot(X[r,:], Wx_l[:,j]); rows r = t*32+b. Layer passed as index.
__global__ __launch_bounds__(256) void k_xh(const int* __restrict__ ids,
                                            int mode, int layer) {
    __shared__ float xs[8][Ee];
    const float* Wxl = g_wx + layer * Ee * Gg;
    const int r0 = blockIdx.x * 8;
    const int tid = threadIdx.x;
    for (int idx = tid; idx < 8 * Ee; idx += 256) {
        int rr = idx >> 7, k = idx & 127;
        int r = r0 + rr;
        float v;
        if (mode == 0) {
            int t = r >> 5, b = r & 31;
            int id = ids[b * Tt + t];
            if (id < 0) id = 0;
            if (id >= Vv) id = Vv - 1;
            v = g_emb[(long)id * Ee + k];
        } else {
            v = g_h0[r * Ee + k];
        }
        xs[rr][k] = v;
    }
    __syncthreads();
    const int j = tid;
    float a0[8], a1[8];
#pragma unroll
    for (int rr = 0; rr < 8; rr++) { a0[rr] = 0.f; a1[rr] = 0.f; }
#pragma unroll 4
    for (int k = 0; k < Ee; k++) {
        float w0 = Wxl[k * Gg + j];
        float w1 = Wxl[k * Gg + j + 256];
#pragma unroll
        for (int rr = 0; rr < 8; rr++) {
            float x = xs[rr][k];
            a0[rr] = fmaf(x, w0, a0[rr]);
            a1[rr] = fmaf(x, w1, a1[rr]);
        }
    }
#pragma unroll
    for (int rr = 0; rr < 8; rr++) {
        g_xh[(r0 + rr) * Gg + j]       = a0[rr];
        g_xh[(r0 + rr) * Gg + j + 256] = a1[rr];
    }
}

#define WK 32
__global__ __launch_bounds__(256) void k_milstm(int layer) {
    __shared__ float hS[Ee];
    __shared__ float gS[Gg];
    const int b = blockIdx.x, j = threadIdx.x;
    const int jB = j + 256;
    const float alA = g_al[layer * Gg + j],  alB = g_al[layer * Gg + jB];
    const float b1A = g_b1[layer * Gg + j],  b1B = g_b1[layer * Gg + jB];
    const float b2A = g_b2[layer * Gg + j],  b2B = g_b2[layer * Gg + jB];
    const float biA = g_bi[layer * Gg + j],  biB = g_bi[layer * Gg + jB];
    float wij = 0.f, wfj = 0.f, woj = 0.f, cc = 0.f;
    if (j < Ee) {
        wij = g_wi[layer * Ee + j];
        wfj = g_wf[layer * Ee + j];
        woj = g_wo[layer * Ee + j];
        hS[j] = 0.f;
    }
    const float* wA = g_whT + (layer * Gg + j)  * Ee;
    const float* wB = g_whT + (layer * Gg + jB) * Ee;
    float rA[WK], rB[WK];
#pragma unroll
    for (int k = 0; k < WK; k++) { rA[k] = wA[k]; rB[k] = wB[k]; }
    __syncthreads();
    float* outp = layer ? g_h1 : g_h0;

    for (int t = 0; t < Tt; t++) {
        const int base = (t * Bb + b) * Gg;
        float xhA = g_xh[base + j];
        float xhB = g_xh[base + jB];
        float sA = 0.f, sB = 0.f;
#pragma unroll
        for (int k = 0; k < WK; k++) {
            float h = hS[k];
            sA = fmaf(h, rA[k], sA);
            sB = fmaf(h, rB[k], sB);
        }
#pragma unroll 8
        for (int k = WK; k < Ee; k++) {
            float h = hS[k];
            sA = fmaf(h, wA[k], sA);
            sB = fmaf(h, wB[k], sB);
        }
        gS[j]  = fmaf(alA * xhA, sA, fmaf(b1A, xhA, fmaf(b2A, sA, biA)));
        gS[jB] = fmaf(alB * xhB, sB, fmaf(b1B, xhB, fmaf(b2B, sB, biB)));
        __syncthreads();
        if (j < Ee) {
            float gi = gS[j]          + wij * cc;
            float gj = gS[Ee + j];
            float gf = gS[2 * Ee + j] + wfj * cc;
            float c_new = sigf(gf + 1.0f) * cc + sigf(gi) * tanhf(gj);
            float go = gS[3 * Ee + j] + woj * c_new;
            float h_new = sigf(go) * tanhf(c_new);
            cc = c_new;
            hS[j] = h_new;
            if (layer) outp[(b * Tt + t) * Ee + j] = h_new;
            else       outp[(t * Bb + b) * Ee + j] = h_new;
        }
        __syncthreads();
    }
}

__global__ void k_vh1() {
    long i0 = (long)blockIdx.x * blockDim.x + threadIdx.x;
    long st = (long)gridDim.x * blockDim.x;
    int f = 0;
    for (long i = i0; i < (long)Bb * Tt * Ee; i += st) {
        float v = g_h1[i];
        if (isfinite(v)) { if (v != 0.f) f |= 1; }
        else f |= 2;
    }
    if (f) atomicOr(&g_flag, f);
}

// logits: block = (256 v-cols, 16 m-rows); coalesced swT loads; guarded f32 out
__global__ __launch_bounds__(256) void k_logits2(float* __restrict__ out,
                                                 long nout) {
    __shared__ float hS2[16][Ee];
    const int tid = threadIdx.x;
    const int v = blockIdx.x * 256 + tid;
    const int m0 = blockIdx.y * 16;
    for (int idx = tid; idx < 16 * Ee; idx += 256) {
        int mm = idx >> 7, k = idx & 127;
        hS2[mm][k] = g_h1[(long)(m0 + mm) * Ee + k];
    }
    __syncthreads();
    float acc[16];
#pragma unroll
    for (int mm = 0; mm < 16; mm++) acc[mm] = 0.f;
#pragma unroll 4
    for (int k = 0; k < Ee; k++) {
        float w = g_swT[(long)k * Vv + v];
#pragma unroll
        for (int mm = 0; mm < 16; mm++) acc[mm] = fmaf(hS2[mm][k], w, acc[mm]);
    }
    float bias = g_sb[v];
#pragma unroll
    for (int mm = 0; mm < 16; mm++) {
        long o = (long)(m0 + mm) * Vv + v;
        if (o < nout) out[o] = acc[mm] + bias;
    }
}

__global__ void k_beacon(unsigned* __restrict__ out) {
    if ((g_flag & 1) == 0 || (g_flag & 2)) out[0] = 0x7FC07FC0u;
}

// ---------------------------------------------------------------------------
extern "C" void kernel_launch(void* const* d_in, const int* in_sizes, int n_in,
                              void* d_out, int out_size) {
    long nout = (long)out_size;

    static const int sigE[13]  = {4096, 4096000, 131072, 131072, 1024, 1024,
                                  1024, 1024, 256, 256, 256, 4096000, 32000};
    static const int alphE[13] = {131072, 131072, 1024, 1024, 1024, 1024,
                                  4096000, 4096, 32000, 4096000, 256, 256, 256};
    int m_sigE = (n_in == 13), m_alphE = (n_in == 13);
    int m_sigB = (n_in == 13), m_alphB = (n_in == 13);
    for (int i = 0; i < 13 && i < n_in; i++) {
        if (in_sizes[i] != sigE[i])      m_sigE = 0;
        if (in_sizes[i] != alphE[i])     m_alphE = 0;
        if (in_sizes[i] != 4 * sigE[i])  m_sigB = 0;
        if (in_sizes[i] != 4 * alphE[i]) m_alphB = 0;
    }

    const void *ids = 0, *emb = 0, *Wx = 0, *Wh = 0, *al = 0, *b1 = 0, *b2 = 0,
               *bi = 0, *wi = 0, *wf = 0, *wo = 0, *sw = 0, *sb = 0;
    if (m_sigE || m_sigB) {
        ids = d_in[0]; emb = d_in[1]; Wx = d_in[2]; Wh = d_in[3];
        al = d_in[4]; b1 = d_in[5]; b2 = d_in[6]; bi = d_in[7];
        wi = d_in[8]; wf = d_in[9]; wo = d_in[10]; sw = d_in[11]; sb = d_in[12];
    } else if (m_alphE || m_alphB) {
        Wh = d_in[0]; Wx = d_in[1]; al = d_in[2]; b1 = d_in[3]; b2 = d_in[4];
        bi = d_in[5]; emb = d_in[6]; ids = d_in[7]; sb = d_in[8]; sw = d_in[9];
        wf = d_in[10]; wi = d_in[11]; wo = d_in[12];
    } else if (n_in >= 13) {
        // unit-agnostic greedy: classify by size multiplicity
        int maxs = 0;
        for (int i = 0; i < n_in; i++) if (in_sizes[i] > maxs) maxs = in_sizes[i];
        int cnt4 = -1, cnt3 = -1;               // sizes appearing 4x / 3x
        for (int i = 0; i < n_in; i++) {
            int c = 0;
            for (int k2 = 0; k2 < n_in; k2++) if (in_sizes[k2] == in_sizes[i]) c++;
            if (c == 4) cnt4 = in_sizes[i];
            if (c == 3) cnt3 = in_sizes[i];
        }
        int nG = 0, nP = 0, nBig = 0, nMid = 0;
        int mid = -1;                            // the 2x size that's not maxs
        for (int i = 0; i < n_in; i++) {
            int s = in_sizes[i];
            if (s == maxs || s == cnt4 || s == cnt3) continue;
            int c = 0;
            for (int k2 = 0; k2 < n_in; k2++) if (in_sizes[k2] == s) c++;
            if (c == 2) mid = s;
        }
        const void* singles[2] = {0, 0}; int ssz[2] = {0, 0}; int nS = 0;
        for (int i = 0; i < n_in; i++) {
            int s = in_sizes[i]; const void* p = d_in[i];
            if (s == maxs)      { if (nBig++ == 0) emb = p; else sw = p; }
            else if (s == mid)  { if (nMid++ == 0) Wx = p; else Wh = p; }
            else if (s == cnt4) { if (nG == 0) al = p; else if (nG == 1) b1 = p;
                                  else if (nG == 2) b2 = p; else bi = p; nG++; }
            else if (s == cnt3) { if (nP == 0) wi = p; else if (nP == 1) wf = p;
                                  else wo = p; nP++; }
            else if (nS < 2)    { singles[nS] = p; ssz[nS] = s; nS++; }
        }
        if (nS == 2) {                           // smaller single = ids, larger = sb
            if (ssz[0] < ssz[1]) { ids = singles[0]; sb = singles[1]; }
            else                 { ids = singles[1]; sb = singles[0]; }
        }
    }

    k_reset<<<1, 1>>>();
    if (!ids || !emb || !sw || !Wx || !Wh || !al || !b1 || !b2 || !bi ||
        !wi || !wf || !wo || !sb) {
        k_beacon<<<1, 1>>>((unsigned*)d_out);    // bind failure -> nan
        return;
    }

    k_probe<<<1, 1>>>((const unsigned*)al);

    k_conv_sel<<<4096, 256>>>(emb, (long)Vv * Ee, 0);
    k_swT<<<8192, 256>>>(sw);
    k_conv_sel<<<512, 256>>>(Wx, Ll * Ee * Gg, 1);
    k_conv_sel<<<512, 256>>>(Wh, Ll * Ee * Gg, 2);
    k_conv_sel<<<4, 256>>>(al, Ll * Gg, 3);
    k_conv_sel<<<4, 256>>>(b1, Ll * Gg, 4);
    k_conv_sel<<<4, 256>>>(b2, Ll * Gg, 5);
    k_conv_sel<<<4, 256>>>(bi, Ll * Gg, 6);
    k_conv_sel<<<1, 256>>>(wi, Ll * Ee, 7);
    k_conv_sel<<<1, 256>>>(wf, Ll * Ee, 8);
    k_conv_sel<<<1, 256>>>(wo, Ll * Ee, 9);
    k_conv_sel<<<125, 256>>>(sb, Vv, 10);

    k_transpose_wh<<<Ll * Gg, Ee>>>();

    k_xh<<<(Tt * Bb) / 8, 256>>>((const int*)ids, 0, 0);
    k_milstm<<<Bb, 256>>>(0);
    k_xh<<<(Tt * Bb) / 8, 256>>>((const int*)ids, 1, 1);
    k_milstm<<<Bb, 256>>>(1);

    k_vh1<<<64, 256>>>();

    dim3 grid(Vv / 256, (Bb * Tt) / 16);
    k_logits2<<<grid, 256>>>((float*)d_out, nout);

    k_beacon<<<1, 1>>>((unsigned*)d_out);
}

// round 14
// speedup vs baseline: 1.0411x; 1.0411x over previous
#include <cuda_runtime.h>
#include <cuda_bf16.h>
#include <cuda_fp16.h>
#include <mma.h>

namespace wm = nvcuda::wmma;

#define Vv 32000
#define Ee 128
#define Bb 32
#define Tt 128
#define Gg 512
#define Ll 2

// ---- device globals (referenced ONLY inside device code) ----
__device__ float g_emb[Vv * Ee];
__device__ __nv_bfloat16 g_swH[Vv * Ee];   // softmax_w hi (bf16), [v][k]
__device__ __nv_bfloat16 g_swL[Vv * Ee];   // softmax_w lo (bf16), [v][k]
__device__ float g_wx [Ll * Ee * Gg];
__device__ float g_al [Ll * Gg];
__device__ float g_b1 [Ll * Gg];
__device__ float g_b2 [Ll * Gg];
__device__ float g_bi [Ll * Gg];
__device__ float g_wi [Ll * Ee];
__device__ float g_wf [Ll * Ee];
__device__ float g_wo [Ll * Ee];
__device__ float g_sb [Vv];
__device__ float g_xh [Tt * Bb * Gg];
__device__ float g_h0 [Tt * Bb * Ee];
__device__ float g_h1 [Bb * Tt * Ee];
__device__ float g_whT[Ll * Gg * Ee];

__device__ __forceinline__ float sigf(float x) { return 1.0f / (1.0f + __expf(-x)); }

__device__ __forceinline__ int probe_dt(const void* al) {
    unsigned v = *(const unsigned*)al;
    if (v == 0x3F803F80u) return 1;      // bf16
    if (v == 0x3C003C00u) return 2;      // f16
    return 0;                            // f32
}
__device__ __forceinline__ float load_as_f32(const void* src, long i, int dt) {
    if (dt == 1) return __bfloat162float(((const __nv_bfloat16*)src)[i]);
    if (dt == 2) return __half2float(((const __half*)src)[i]);
    return ((const float*)src)[i];
}

// ---------------------------------------------------------------------------
// Fused prep: all conversions + Wh transpose + softmax_w hi/lo split.
// Segments by blockIdx.  9188 blocks x 256 threads.
// ---------------------------------------------------------------------------
#define PB_EMB 4000
#define PB_SW  4000
#define PB_WX  128
#define PB_WHT 1024
#define PB_SMALL 37
#define PB_TOTAL (PB_EMB + PB_SW + PB_WX + PB_WHT + PB_SMALL)

__global__ __launch_bounds__(256) void k_prep(
    const void* __restrict__ emb, const void* __restrict__ sw,
    const void* __restrict__ Wx,  const void* __restrict__ Wh,
    const void* __restrict__ al,  const void* __restrict__ b1,
    const void* __restrict__ b2,  const void* __restrict__ bi,
    const void* __restrict__ wi,  const void* __restrict__ wf,
    const void* __restrict__ wo,  const void* __restrict__ sb) {
    const int dt = probe_dt(al);
    int bb = blockIdx.x;
    const int tid = threadIdx.x;
    if (bb < PB_EMB) {                                   // emb conversion
        long base = (long)bb * 1024;
        for (int it = 0; it < 4; it++) {
            long i = base + tid + it * 256;
            g_emb[i] = load_as_f32(emb, i, dt);
        }
        return;
    }
    bb -= PB_EMB;
    if (bb < PB_SW) {                                    // softmax_w hi/lo split
        long base = (long)bb * 1024;
        for (int it = 0; it < 4; it++) {
            long i = base + tid + it * 256;
            float x = load_as_f32(sw, i, dt);
            __nv_bfloat16 h = __float2bfloat16(x);
            g_swH[i] = h;
            g_swL[i] = __float2bfloat16(x - __bfloat162float(h));
        }
        return;
    }
    bb -= PB_SW;
    if (bb < PB_WX) {                                    // Wx conversion
        long base = (long)bb * 1024;
        for (int it = 0; it < 4; it++) {
            long i = base + tid + it * 256;
            g_wx[i] = load_as_f32(Wx, i, dt);
        }
        return;
    }
    bb -= PB_WX;
    if (bb < PB_WHT) {                                   // Wh conv+transpose
        int l = bb >> 9, j = bb & 511;
        if (tid < Ee)
            g_whT[bb * Ee + tid] =
                load_as_f32(Wh, (long)l * Ee * Gg + (long)tid * Gg + j, dt);
        return;
    }
    bb -= PB_WHT;
    {                                                    // small params
        long e = (long)bb * 1024 + tid;
        for (int it = 0; it < 4; it++, e += 256) {
            if (e < 1024)       g_al[e]        = load_as_f32(al, e, dt);
            else if (e < 2048)  g_b1[e - 1024] = load_as_f32(b1, e - 1024, dt);
            else if (e < 3072)  g_b2[e - 2048] = load_as_f32(b2, e - 2048, dt);
            else if (e < 4096)  g_bi[e - 3072] = load_as_f32(bi, e - 3072, dt);
            else if (e < 4352)  g_wi[e - 4096] = load_as_f32(wi, e - 4096, dt);
            else if (e < 4608)  g_wf[e - 4352] = load_as_f32(wf, e - 4352, dt);
            else if (e < 4864)  g_wo[e - 4608] = load_as_f32(wo, e - 4608, dt);
            else if (e < 36864) g_sb[e - 4864] = load_as_f32(sb, e - 4864, dt);
        }
    }
}

// ---------------------------------------------------------------------------
// XH[r][j] = dot(X[r,:], Wx_l[:,j]); rows r = t*32+b.
// ---------------------------------------------------------------------------
__global__ __launch_bounds__(256) void k_xh(const int* __restrict__ ids,
                                            int mode, int layer) {
    __shared__ float xs[8][Ee];
    const float* Wxl = g_wx + layer * Ee * Gg;
    const int r0 = blockIdx.x * 8;
    const int tid = threadIdx.x;
    for (int idx = tid; idx < 8 * Ee; idx += 256) {
        int rr = idx >> 7, k = idx & 127;
        int r = r0 + rr;
        float v;
        if (mode == 0) {
            int t = r >> 5, b = r & 31;
            int id = ids[b * Tt + t];
            if (id < 0) id = 0;
            if (id >= Vv) id = Vv - 1;
            v = g_emb[(long)id * Ee + k];
        } else {
            v = g_h0[r * Ee + k];
        }
        xs[rr][k] = v;
    }
    __syncthreads();
    const int j = tid;
    float a0[8], a1[8];
#pragma unroll
    for (int rr = 0; rr < 8; rr++) { a0[rr] = 0.f; a1[rr] = 0.f; }
#pragma unroll 4
    for (int k = 0; k < Ee; k++) {
        float w0 = Wxl[k * Gg + j];
        float w1 = Wxl[k * Gg + j + 256];
#pragma unroll
        for (int rr = 0; rr < 8; rr++) {
            float x = xs[rr][k];
            a0[rr] = fmaf(x, w0, a0[rr]);
            a1[rr] = fmaf(x, w1, a1[rr]);
        }
    }
#pragma unroll
    for (int rr = 0; rr < 8; rr++) {
        g_xh[(r0 + rr) * Gg + j]       = a0[rr];
        g_xh[(r0 + rr) * Gg + j + 256] = a1[rr];
    }
}

// ---------------------------------------------------------------------------
// miLSTM recurrence (unchanged from passing R13).
// ---------------------------------------------------------------------------
#define WK 32
__global__ __launch_bounds__(256) void k_milstm(int layer) {
    __shared__ float hS[Ee];
    __shared__ float gS[Gg];
    const int b = blockIdx.x, j = threadIdx.x;
    const int jB = j + 256;
    const float alA = g_al[layer * Gg + j],  alB = g_al[layer * Gg + jB];
    const float b1A = g_b1[layer * Gg + j],  b1B = g_b1[layer * Gg + jB];
    const float b2A = g_b2[layer * Gg + j],  b2B = g_b2[layer * Gg + jB];
    const float biA = g_bi[layer * Gg + j],  biB = g_bi[layer * Gg + jB];
    float wij = 0.f, wfj = 0.f, woj = 0.f, cc = 0.f;
    if (j < Ee) {
        wij = g_wi[layer * Ee + j];
        wfj = g_wf[layer * Ee + j];
        woj = g_wo[layer * Ee + j];
        hS[j] = 0.f;
    }
    const float* wA = g_whT + (layer * Gg + j)  * Ee;
    const float* wB = g_whT + (layer * Gg + jB) * Ee;
    float rA[WK], rB[WK];
#pragma unroll
    for (int k = 0; k < WK; k++) { rA[k] = wA[k]; rB[k] = wB[k]; }
    __syncthreads();
    float* outp = layer ? g_h1 : g_h0;

    for (int t = 0; t < Tt; t++) {
        const int base = (t * Bb + b) * Gg;
        float xhA = g_xh[base + j];
        float xhB = g_xh[base + jB];
        float sA = 0.f, sB = 0.f;
#pragma unroll
        for (int k = 0; k < WK; k++) {
            float h = hS[k];
            sA = fmaf(h, rA[k], sA);
            sB = fmaf(h, rB[k], sB);
        }
#pragma unroll 8
        for (int k = WK; k < Ee; k++) {
            float h = hS[k];
            sA = fmaf(h, wA[k], sA);
            sB = fmaf(h, wB[k], sB);
        }
        gS[j]  = fmaf(alA * xhA, sA, fmaf(b1A, xhA, fmaf(b2A, sA, biA)));
        gS[jB] = fmaf(alB * xhB, sB, fmaf(b1B, xhB, fmaf(b2B, sB, biB)));
        __syncthreads();
        if (j < Ee) {
            float gi = gS[j]          + wij * cc;
            float gj = gS[Ee + j];
            float gf = gS[2 * Ee + j] + wfj * cc;
            float c_new = sigf(gf + 1.0f) * cc + sigf(gi) * tanhf(gj);
            float go = gS[3 * Ee + j] + woj * c_new;
            float h_new = sigf(go) * tanhf(c_new);
            cc = c_new;
            hS[j] = h_new;
            if (layer) outp[(b * Tt + t) * Ee + j] = h_new;
            else       outp[(t * Bb + b) * Ee + j] = h_new;
        }
        __syncthreads();
    }
}

// ---------------------------------------------------------------------------
// logits: bf16 WMMA m16n16k16 with 3-term hi/lo split (fp32 accumulators).
// 64(M)x64(N) tile, K in 2 chunks of 64. A split in-kernel; B pre-split.
// Static smem 36.9 KB. rel err ~1e-5.
// ---------------------------------------------------------------------------
#define LDA 72
#define LDC 68
__global__ __launch_bounds__(256) void k_logits(float* __restrict__ out,
                                                long nout) {
    __shared__ __align__(32) char smem_raw[4 * 64 * LDA * 2];   // 36864 B
    __nv_bfloat16* Ah = reinterpret_cast<__nv_bfloat16*>(smem_raw);
    __nv_bfloat16* Al = Ah + 64 * LDA;
    __nv_bfloat16* Bh = Al + 64 * LDA;
    __nv_bfloat16* Bl = Bh + 64 * LDA;
    const int n0 = blockIdx.x * 64, m0 = blockIdx.y * 64;
    const int tid = threadIdx.x;
    const int w = tid >> 5;
    const int wm = (w & 1) * 32;          // 2x4 warp grid over 64x64
    const int wn = (w >> 1) * 16;

    wm::fragment<wm::accumulator, 16, 16, 16, float> cf[2];
#pragma unroll
    for (int i = 0; i < 2; i++) wm::fill_fragment(cf[i], 0.f);

#pragma unroll
    for (int kc = 0; kc < Ee; kc += 64) {
        // stage A (fp32 -> hi/lo split): 64 rows x 64 k
#pragma unroll
        for (int it = 0; it < 16; it++) {
            int idx = tid + it * 256;                 // 0..4095
            int r = idx >> 6, k = idx & 63;
            float x = g_h1[(long)(m0 + r) * Ee + kc + k];
            __nv_bfloat16 h = __float2bfloat16(x);
            Ah[r * LDA + k] = h;
            Al[r * LDA + k] = __float2bfloat16(x - __bfloat162float(h));
        }
        // stage B (pre-split bf16, copy as uint pairs): 64 rows x 32 uints
#pragma unroll
        for (int it = 0; it < 8; it++) {
            int idx = tid + it * 256;                 // 0..2047
            int r = idx >> 5, c2 = idx & 31;
            long src = (long)(n0 + r) * 64 + (kc >> 1) + c2;   // uint index
            unsigned vh = reinterpret_cast<const unsigned*>(g_swH)[src];
            unsigned vl = reinterpret_cast<const unsigned*>(g_swL)[src];
            reinterpret_cast<unsigned*>(Bh + r * LDA)[c2] = vh;
            reinterpret_cast<unsigned*>(Bl + r * LDA)[c2] = vl;
        }
        __syncthreads();

#pragma unroll
        for (int kf = 0; kf < 4; kf++) {
            wm::fragment<wm::matrix_b, 16, 16, 16, __nv_bfloat16, wm::col_major> bh, bl;
            wm::load_matrix_sync(bh, Bh + wn * LDA + kf * 16, LDA);
            wm::load_matrix_sync(bl, Bl + wn * LDA + kf * 16, LDA);
#pragma unroll
            for (int i = 0; i < 2; i++) {
                wm::fragment<wm::matrix_a, 16, 16, 16, __nv_bfloat16, wm::row_major> ah, alo;
                wm::load_matrix_sync(ah,  Ah + (wm + i * 16) * LDA + kf * 16, LDA);
                wm::load_matrix_sync(alo, Al + (wm + i * 16) * LDA + kf * 16, LDA);
                wm::mma_sync(cf[i], ah,  bh, cf[i]);
                wm::mma_sync(cf[i], ah,  bl, cf[i]);
                wm::mma_sync(cf[i], alo, bh, cf[i]);
            }
        }
        __syncthreads();
    }

    // epilogue: park C in smem (reuse), add bias, guarded coalesced stores
    float* Cs = reinterpret_cast<float*>(smem_raw);
#pragma unroll
    for (int i = 0; i < 2; i++)
        wm::store_matrix_sync(Cs + (wm + i * 16) * LDC + wn, cf[i], LDC,
                              wm::mem_row_major);
    __syncthreads();
#pragma unroll
    for (int it = 0; it < 16; it++) {
        int idx = tid + it * 256;                     // 0..4095 over 64x64
        int r = idx >> 6, c = idx & 63;
        long o = (long)(m0 + r) * Vv + n0 + c;
        if (o < nout) out[o] = Cs[r * LDC + c] + g_sb[n0 + c];
    }
}

// ---------------------------------------------------------------------------
extern "C" void kernel_launch(void* const* d_in, const int* in_sizes, int n_in,
                              void* d_out, int out_size) {
    long nout = (long)out_size;

    static const int sigE[13]  = {4096, 4096000, 131072, 131072, 1024, 1024,
                                  1024, 1024, 256, 256, 256, 4096000, 32000};
    static const int alphE[13] = {131072, 131072, 1024, 1024, 1024, 1024,
                                  4096000, 4096, 32000, 4096000, 256, 256, 256};
    int m_sigE = (n_in == 13), m_alphE = (n_in == 13);
    int m_sigB = (n_in == 13), m_alphB = (n_in == 13);
    for (int i = 0; i < 13 && i < n_in; i++) {
        if (in_sizes[i] != sigE[i])      m_sigE = 0;
        if (in_sizes[i] != alphE[i])     m_alphE = 0;
        if (in_sizes[i] != 4 * sigE[i])  m_sigB = 0;
        if (in_sizes[i] != 4 * alphE[i]) m_alphB = 0;
    }

    const void *ids = 0, *emb = 0, *Wx = 0, *Wh = 0, *al = 0, *b1 = 0, *b2 = 0,
               *bi = 0, *wi = 0, *wf = 0, *wo = 0, *sw = 0, *sb = 0;
    if (m_sigE || m_sigB) {
        ids = d_in[0]; emb = d_in[1]; Wx = d_in[2]; Wh = d_in[3];
        al = d_in[4]; b1 = d_in[5]; b2 = d_in[6]; bi = d_in[7];
        wi = d_in[8]; wf = d_in[9]; wo = d_in[10]; sw = d_in[11]; sb = d_in[12];
    } else if (m_alphE || m_alphB) {
        Wh = d_in[0]; Wx = d_in[1]; al = d_in[2]; b1 = d_in[3]; b2 = d_in[4];
        bi = d_in[5]; emb = d_in[6]; ids = d_in[7]; sb = d_in[8]; sw = d_in[9];
        wf = d_in[10]; wi = d_in[11]; wo = d_in[12];
    } else if (n_in >= 13) {
        int maxs = 0;
        for (int i = 0; i < n_in; i++) if (in_sizes[i] > maxs) maxs = in_sizes[i];
        int cnt4 = -1, cnt3 = -1;
        for (int i = 0; i < n_in; i++) {
            int c = 0;
            for (int k2 = 0; k2 < n_in; k2++) if (in_sizes[k2] == in_sizes[i]) c++;
            if (c == 4) cnt4 = in_sizes[i];
            if (c == 3) cnt3 = in_sizes[i];
        }
        int nG = 0, nP = 0, nBig = 0, nMid = 0;
        int mid = -1;
        for (int i = 0; i < n_in; i++) {
            int s = in_sizes[i];
            if (s == maxs || s == cnt4 || s == cnt3) continue;
            int c = 0;
            for (int k2 = 0; k2 < n_in; k2++) if (in_sizes[k2] == s) c++;
            if (c == 2) mid = s;
        }
        const void* singles[2] = {0, 0}; int ssz[2] = {0, 0}; int nS = 0;
        for (int i = 0; i < n_in; i++) {
            int s = in_sizes[i]; const void* p = d_in[i];
            if (s == maxs)      { if (nBig++ == 0) emb = p; else sw = p; }
            else if (s == mid)  { if (nMid++ == 0) Wx = p; else Wh = p; }
            else if (s == cnt4) { if (nG == 0) al = p; else if (nG == 1) b1 = p;
                                  else if (nG == 2) b2 = p; else bi = p; nG++; }
            else if (s == cnt3) { if (nP == 0) wi = p; else if (nP == 1) wf = p;
                                  else wo = p; nP++; }
            else if (nS < 2)    { singles[nS] = p; ssz[nS] = s; nS++; }
        }
        if (nS == 2) {
            if (ssz[0] < ssz[1]) { ids = singles[0]; sb = singles[1]; }
            else                 { ids = singles[1]; sb = singles[0]; }
        }
    }
    if (!ids || !emb || !sw || !Wx || !Wh || !al || !b1 || !b2 || !bi ||
        !wi || !wf || !wo || !sb) return;

    // launch 1: fused prep (conversions + whT + sw split)
    k_prep<<<PB_TOTAL, 256>>>(emb, sw, Wx, Wh, al, b1, b2, bi, wi, wf, wo, sb);

    // launches 2-5: recurrence
    k_xh<<<(Tt * Bb) / 8, 256>>>((const int*)ids, 0, 0);
    k_milstm<<<Bb, 256>>>(0);
    k_xh<<<(Tt * Bb) / 8, 256>>>((const int*)ids, 1, 1);
    k_milstm<<<Bb, 256>>>(1);

    // launch 6 (ncu -s 5 captures this one): tensor-core logits
    dim3 grid(Vv / 64, (Bb * Tt) / 64);
    k_logits<<<grid, 256>>>((float*)d_out, nout);
}

// round 15
// speedup vs baseline: 5.2972x; 5.0881x over previous
#include <cuda_runtime.h>
#include <cuda_bf16.h>
#include <cuda_fp16.h>
#include <mma.h>

namespace wm = nvcuda::wmma;

#define Vv 32000
#define Ee 128
#define Bb 32
#define Tt 128
#define Gg 512
#define Ll 2

// ---- device globals (referenced ONLY inside device code) ----
__device__ float g_emb[Vv * Ee];
__device__ __nv_bfloat16 g_swH[Vv * Ee];   // softmax_w hi (bf16), [v][k]
__device__ __nv_bfloat16 g_swL[Vv * Ee];   // softmax_w lo (bf16), [v][k]
__device__ float g_wx [Ll * Ee * Gg];
__device__ float g_wh [Ll * Ee * Gg];      // Wh in ORIGINAL [l][k][j] layout
__device__ float g_al [Ll * Gg];
__device__ float g_b1 [Ll * Gg];
__device__ float g_b2 [Ll * Gg];
__device__ float g_bi [Ll * Gg];
__device__ float g_wi [Ll * Ee];
__device__ float g_wf [Ll * Ee];
__device__ float g_wo [Ll * Ee];
__device__ float g_sb [Vv];
__device__ float g_xh [Tt * Bb * Gg];
__device__ float g_h0 [Tt * Bb * Ee];
__device__ float g_h1 [Bb * Tt * Ee];

__device__ __forceinline__ float sigf(float x) { return 1.0f / (1.0f + __expf(-x)); }

__device__ __forceinline__ int probe_dt(const void* al) {
    unsigned v = *(const unsigned*)al;
    if (v == 0x3F803F80u) return 1;      // bf16
    if (v == 0x3C003C00u) return 2;      // f16
    return 0;                            // f32
}
__device__ __forceinline__ float load_as_f32(const void* src, long i, int dt) {
    if (dt == 1) return __bfloat162float(((const __nv_bfloat16*)src)[i]);
    if (dt == 2) return __half2float(((const __half*)src)[i]);
    return ((const float*)src)[i];
}

// ---------------------------------------------------------------------------
// Fused prep: conversions + softmax_w hi/lo split. Segments by blockIdx.
// ---------------------------------------------------------------------------
#define PB_EMB 4000
#define PB_SW  4000
#define PB_WX  128
#define PB_WH  128
#define PB_SMALL 37
#define PB_TOTAL (PB_EMB + PB_SW + PB_WX + PB_WH + PB_SMALL)

__global__ __launch_bounds__(256) void k_prep(
    const void* __restrict__ emb, const void* __restrict__ sw,
    const void* __restrict__ Wx,  const void* __restrict__ Wh,
    const void* __restrict__ al,  const void* __restrict__ b1,
    const void* __restrict__ b2,  const void* __restrict__ bi,
    const void* __restrict__ wi,  const void* __restrict__ wf,
    const void* __restrict__ wo,  const void* __restrict__ sb) {
    const int dt = probe_dt(al);
    int bb = blockIdx.x;
    const int tid = threadIdx.x;
    if (bb < PB_EMB) {
        long base = (long)bb * 1024;
        for (int it = 0; it < 4; it++) {
            long i = base + tid + it * 256;
            g_emb[i] = load_as_f32(emb, i, dt);
        }
        return;
    }
    bb -= PB_EMB;
    if (bb < PB_SW) {                                    // hi/lo split
        long base = (long)bb * 1024;
        for (int it = 0; it < 4; it++) {
            long i = base + tid + it * 256;
            float x = load_as_f32(sw, i, dt);
            __nv_bfloat16 h = __float2bfloat16(x);
            g_swH[i] = h;
            g_swL[i] = __float2bfloat16(x - __bfloat162float(h));
        }
        return;
    }
    bb -= PB_SW;
    if (bb < PB_WX) {
        long base = (long)bb * 1024;
        for (int it = 0; it < 4; it++) {
            long i = base + tid + it * 256;
            g_wx[i] = load_as_f32(Wx, i, dt);
        }
        return;
    }
    bb -= PB_WX;
    if (bb < PB_WH) {                                    // Wh natural layout
        long base = (long)bb * 1024;
        for (int it = 0; it < 4; it++) {
            long i = base + tid + it * 256;
            g_wh[i] = load_as_f32(Wh, i, dt);
        }
        return;
    }
    bb -= PB_WH;
    {                                                    // small params
        long e = (long)bb * 1024 + tid;
        for (int it = 0; it < 4; it++, e += 256) {
            if (e < 1024)       g_al[e]        = load_as_f32(al, e, dt);
            else if (e < 2048)  g_b1[e - 1024] = load_as_f32(b1, e - 1024, dt);
            else if (e < 3072)  g_b2[e - 2048] = load_as_f32(b2, e - 2048, dt);
            else if (e < 4096)  g_bi[e - 3072] = load_as_f32(bi, e - 3072, dt);
            else if (e < 4352)  g_wi[e - 4096] = load_as_f32(wi, e - 4096, dt);
            else if (e < 4608)  g_wf[e - 4352] = load_as_f32(wf, e - 4352, dt);
            else if (e < 4864)  g_wo[e - 4608] = load_as_f32(wo, e - 4608, dt);
            else if (e < 36864) g_sb[e - 4864] = load_as_f32(sb, e - 4864, dt);
        }
    }
}

// ---------------------------------------------------------------------------
// XH[r][j] = dot(X[r,:], Wx_l[:,j]); rows r = t*32+b.
// ---------------------------------------------------------------------------
__global__ __launch_bounds__(256) void k_xh(const int* __restrict__ ids,
                                            int mode, int layer) {
    __shared__ float xs[8][Ee];
    const float* Wxl = g_wx + layer * Ee * Gg;
    const int r0 = blockIdx.x * 8;
    const int tid = threadIdx.x;
    for (int idx = tid; idx < 8 * Ee; idx += 256) {
        int rr = idx >> 7, k = idx & 127;
        int r = r0 + rr;
        float v;
        if (mode == 0) {
            int t = r >> 5, b = r & 31;
            int id = ids[b * Tt + t];
            if (id < 0) id = 0;
            if (id >= Vv) id = Vv - 1;
            v = g_emb[(long)id * Ee + k];
        } else {
            v = g_h0[r * Ee + k];
        }
        xs[rr][k] = v;
    }
    __syncthreads();
    const int j = tid;
    float a0[8], a1[8];
#pragma unroll
    for (int rr = 0; rr < 8; rr++) { a0[rr] = 0.f; a1[rr] = 0.f; }
#pragma unroll 4
    for (int k = 0; k < Ee; k++) {
        float w0 = Wxl[k * Gg + j];
        float w1 = Wxl[k * Gg + j + 256];
#pragma unroll
        for (int rr = 0; rr < 8; rr++) {
            float x = xs[rr][k];
            a0[rr] = fmaf(x, w0, a0[rr]);
            a1[rr] = fmaf(x, w1, a1[rr]);
        }
    }
#pragma unroll
    for (int rr = 0; rr < 8; rr++) {
        g_xh[(r0 + rr) * Gg + j]       = a0[rr];
        g_xh[(r0 + rr) * Gg + j + 256] = a1[rr];
    }
}

// ---------------------------------------------------------------------------
// miLSTM recurrence. COALESCED weight access: Wh kept [k][j] so a warp's 32
// lanes read one 128B line per load (8x less L1 sector traffic than the old
// per-thread-column layout). First WK k-slices register-cached across steps.
// ---------------------------------------------------------------------------
#define WK 32
__global__ __launch_bounds__(256) void k_milstm(int layer) {
    __shared__ float hS[Ee];
    __shared__ float gS[Gg];
    const int b = blockIdx.x, j = threadIdx.x;
    const int jB = j + 256;
    const float* Whl = g_wh + layer * Ee * Gg;
    const float alA = g_al[layer * Gg + j],  alB = g_al[layer * Gg + jB];
    const float b1A = g_b1[layer * Gg + j],  b1B = g_b1[layer * Gg + jB];
    const float b2A = g_b2[layer * Gg + j],  b2B = g_b2[layer * Gg + jB];
    const float biA = g_bi[layer * Gg + j],  biB = g_bi[layer * Gg + jB];
    float wij = 0.f, wfj = 0.f, woj = 0.f, cc = 0.f;
    if (j < Ee) {
        wij = g_wi[layer * Ee + j];
        wfj = g_wf[layer * Ee + j];
        woj = g_wo[layer * Ee + j];
        hS[j] = 0.f;
    }
    float rA[WK], rB[WK];
#pragma unroll
    for (int k = 0; k < WK; k++) {       // one-time coalesced fill
        rA[k] = Whl[k * Gg + j];
        rB[k] = Whl[k * Gg + jB];
    }
    __syncthreads();
    float* outp = layer ? g_h1 : g_h0;

    for (int t = 0; t < Tt; t++) {
        const int base = (t * Bb + b) * Gg;
        float xhA = g_xh[base + j];
        float xhB = g_xh[base + jB];
        float sA = 0.f, sB = 0.f;
#pragma unroll
        for (int k = 0; k < WK; k++) {   // register-resident slices
            float h = hS[k];
            sA = fmaf(h, rA[k], sA);
            sB = fmaf(h, rB[k], sB);
        }
#pragma unroll 8
        for (int k = WK; k < Ee; k++) {  // coalesced L1-resident stream
            float h = hS[k];
            sA = fmaf(h, Whl[k * Gg + j],  sA);
            sB = fmaf(h, Whl[k * Gg + jB], sB);
        }
        gS[j]  = fmaf(alA * xhA, sA, fmaf(b1A, xhA, fmaf(b2A, sA, biA)));
        gS[jB] = fmaf(alB * xhB, sB, fmaf(b1B, xhB, fmaf(b2B, sB, biB)));
        __syncthreads();
        if (j < Ee) {
            float gi = gS[j]          + wij * cc;
            float gj = gS[Ee + j];
            float gf = gS[2 * Ee + j] + wfj * cc;
            float c_new = sigf(gf + 1.0f) * cc + sigf(gi) * tanhf(gj);
            float go = gS[3 * Ee + j] + woj * c_new;
            float h_new = sigf(go) * tanhf(c_new);
            cc = c_new;
            hS[j] = h_new;
            if (layer) outp[(b * Tt + t) * Ee + j] = h_new;
            else       outp[(t * Bb + b) * Ee + j] = h_new;
        }
        __syncthreads();
    }
}

// ---------------------------------------------------------------------------
// logits: bf16 WMMA m16n16k16, 3-term hi/lo split, 64x64 tile (unchanged).
// ---------------------------------------------------------------------------
#define LDA 72
#define LDC 68
__global__ __launch_bounds__(256) void k_logits(float* __restrict__ out,
                                                long nout) {
    __shared__ __align__(32) char smem_raw[4 * 64 * LDA * 2];   // 36864 B
    __nv_bfloat16* Ah = reinterpret_cast<__nv_bfloat16*>(smem_raw);
    __nv_bfloat16* Al = Ah + 64 * LDA;
    __nv_bfloat16* Bh = Al + 64 * LDA;
    __nv_bfloat16* Bl = Bh + 64 * LDA;
    const int n0 = blockIdx.x * 64, m0 = blockIdx.y * 64;
    const int tid = threadIdx.x;
    const int w = tid >> 5;
    const int wm = (w & 1) * 32;
    const int wn = (w >> 1) * 16;

    wm::fragment<wm::accumulator, 16, 16, 16, float> cf[2];
#pragma unroll
    for (int i = 0; i < 2; i++) wm::fill_fragment(cf[i], 0.f);

#pragma unroll
    for (int kc = 0; kc < Ee; kc += 64) {
#pragma unroll
        for (int it = 0; it < 16; it++) {
            int idx = tid + it * 256;
            int r = idx >> 6, k = idx & 63;
            float x = g_h1[(long)(m0 + r) * Ee + kc + k];
            __nv_bfloat16 h = __float2bfloat16(x);
            Ah[r * LDA + k] = h;
            Al[r * LDA + k] = __float2bfloat16(x - __bfloat162float(h));
        }
#pragma unroll
        for (int it = 0; it < 8; it++) {
            int idx = tid + it * 256;
            int r = idx >> 5, c2 = idx & 31;
            long src = (long)(n0 + r) * 64 + (kc >> 1) + c2;
            unsigned vh = reinterpret_cast<const unsigned*>(g_swH)[src];
            unsigned vl = reinterpret_cast<const unsigned*>(g_swL)[src];
            reinterpret_cast<unsigned*>(Bh + r * LDA)[c2] = vh;
            reinterpret_cast<unsigned*>(Bl + r * LDA)[c2] = vl;
        }
        __syncthreads();

#pragma unroll
        for (int kf = 0; kf < 4; kf++) {
            wm::fragment<wm::matrix_b, 16, 16, 16, __nv_bfloat16, wm::col_major> bh, bl;
            wm::load_matrix_sync(bh, Bh + wn * LDA + kf * 16, LDA);
            wm::load_matrix_sync(bl, Bl + wn * LDA + kf * 16, LDA);
#pragma unroll
            for (int i = 0; i < 2; i++) {
                wm::fragment<wm::matrix_a, 16, 16, 16, __nv_bfloat16, wm::row_major> ah, alo;
                wm::load_matrix_sync(ah,  Ah + (wm + i * 16) * LDA + kf * 16, LDA);
                wm::load_matrix_sync(alo, Al + (wm + i * 16) * LDA + kf * 16, LDA);
                wm::mma_sync(cf[i], ah,  bh, cf[i]);
                wm::mma_sync(cf[i], ah,  bl, cf[i]);
                wm::mma_sync(cf[i], alo, bh, cf[i]);
            }
        }
        __syncthreads();
    }

    float* Cs = reinterpret_cast<float*>(smem_raw);
#pragma unroll
    for (int i = 0; i < 2; i++)
        wm::store_matrix_sync(Cs + (wm + i * 16) * LDC + wn, cf[i], LDC,
                              wm::mem_row_major);
    __syncthreads();
#pragma unroll
    for (int it = 0; it < 16; it++) {
        int idx = tid + it * 256;
        int r = idx >> 6, c = idx & 63;
        long o = (long)(m0 + r) * Vv + n0 + c;
        if (o < nout) out[o] = Cs[r * LDC + c] + g_sb[n0 + c];
    }
}

// ---------------------------------------------------------------------------
extern "C" void kernel_launch(void* const* d_in, const int* in_sizes, int n_in,
                              void* d_out, int out_size) {
    long nout = (long)out_size;

    static const int sigE[13]  = {4096, 4096000, 131072, 131072, 1024, 1024,
                                  1024, 1024, 256, 256, 256, 4096000, 32000};
    static const int alphE[13] = {131072, 131072, 1024, 1024, 1024, 1024,
                                  4096000, 4096, 32000, 4096000, 256, 256, 256};
    int m_sigE = (n_in == 13), m_alphE = (n_in == 13);
    int m_sigB = (n_in == 13), m_alphB = (n_in == 13);
    for (int i = 0; i < 13 && i < n_in; i++) {
        if (in_sizes[i] != sigE[i])      m_sigE = 0;
        if (in_sizes[i] != alphE[i])     m_alphE = 0;
        if (in_sizes[i] != 4 * sigE[i])  m_sigB = 0;
        if (in_sizes[i] != 4 * alphE[i]) m_alphB = 0;
    }

    const void *ids = 0, *emb = 0, *Wx = 0, *Wh = 0, *al = 0, *b1 = 0, *b2 = 0,
               *bi = 0, *wi = 0, *wf = 0, *wo = 0, *sw = 0, *sb = 0;
    if (m_sigE || m_sigB) {
        ids = d_in[0]; emb = d_in[1]; Wx = d_in[2]; Wh = d_in[3];
        al = d_in[4]; b1 = d_in[5]; b2 = d_in[6]; bi = d_in[7];
        wi = d_in[8]; wf = d_in[9]; wo = d_in[10]; sw = d_in[11]; sb = d_in[12];
    } else if (m_alphE || m_alphB) {
        Wh = d_in[0]; Wx = d_in[1]; al = d_in[2]; b1 = d_in[3]; b2 = d_in[4];
        bi = d_in[5]; emb = d_in[6]; ids = d_in[7]; sb = d_in[8]; sw = d_in[9];
        wf = d_in[10]; wi = d_in[11]; wo = d_in[12];
    } else if (n_in >= 13) {
        int maxs = 0;
        for (int i = 0; i < n_in; i++) if (in_sizes[i] > maxs) maxs = in_sizes[i];
        int cnt4 = -1, cnt3 = -1;
        for (int i = 0; i < n_in; i++) {
            int c = 0;
            for (int k2 = 0; k2 < n_in; k2++) if (in_sizes[k2] == in_sizes[i]) c++;
            if (c == 4) cnt4 = in_sizes[i];
            if (c == 3) cnt3 = in_sizes[i];
        }
        int nG = 0, nP = 0, nBig = 0, nMid = 0;
        int mid = -1;
        for (int i = 0; i < n_in; i++) {
            int s = in_sizes[i];
            if (s == maxs || s == cnt4 || s == cnt3) continue;
            int c = 0;
            for (int k2 = 0; k2 < n_in; k2++) if (in_sizes[k2] == s) c++;
            if (c == 2) mid = s;
        }
        const void* singles[2] = {0, 0}; int ssz[2] = {0, 0}; int nS = 0;
        for (int i = 0; i < n_in; i++) {
            int s = in_sizes[i]; const void* p = d_in[i];
            if (s == maxs)      { if (nBig++ == 0) emb = p; else sw = p; }
            else if (s == mid)  { if (nMid++ == 0) Wx = p; else Wh = p; }
            else if (s == cnt4) { if (nG == 0) al = p; else if (nG == 1) b1 = p;
                                  else if (nG == 2) b2 = p; else bi = p; nG++; }
            else if (s == cnt3) { if (nP == 0) wi = p; else if (nP == 1) wf = p;
                                  else wo = p; nP++; }
            else if (nS < 2)    { singles[nS] = p; ssz[nS] = s; nS++; }
        }
        if (nS == 2) {
            if (ssz[0] < ssz[1]) { ids = singles[0]; sb = singles[1]; }
            else                 { ids = singles[1]; sb = singles[0]; }
        }
    }
    if (!ids || !emb || !sw || !Wx || !Wh || !al || !b1 || !b2 || !bi ||
        !wi || !wf || !wo || !sb) return;

    k_prep<<<PB_TOTAL, 256>>>(emb, sw, Wx, Wh, al, b1, b2, bi, wi, wf, wo, sb);

    k_xh<<<(Tt * Bb) / 8, 256>>>((const int*)ids, 0, 0);
    k_milstm<<<Bb, 256>>>(0);
    k_xh<<<(Tt * Bb) / 8, 256>>>((const int*)ids, 1, 1);
    k_milstm<<<Bb, 256>>>(1);

    // launch 6 (ncu -s 5 captures this): tensor-core logits
    dim3 grid(Vv / 64, (Bb * Tt) / 64);
    k_logits<<<grid, 256>>>((float*)d_out, nout);
}

// round 16
// speedup vs baseline: 5.9548x; 1.1241x over previous
#include <cuda_runtime.h>
#include <cuda_bf16.h>
#include <cuda_fp16.h>
#include <mma.h>

namespace wm = nvcuda::wmma;

#define Vv 32000
#define Ee 128
#define Bb 32
#define Tt 128
#define Gg 512
#define Ll 2

// ---- device globals (referenced ONLY inside device code) ----
__device__ __align__(256) float g_emb[Vv * Ee];
__device__ __align__(256) __nv_bfloat16 g_swH[Vv * Ee];
__device__ __align__(256) __nv_bfloat16 g_swL[Vv * Ee];
__device__ __align__(256) float g_wx [Ll * Ee * Gg];
__device__ __align__(256) float g_wh [Ll * Ee * Gg];   // natural [l][k][j]
__device__ __align__(256) float g_al [Ll * Gg];
__device__ __align__(256) float g_b1 [Ll * Gg];
__device__ __align__(256) float g_b2 [Ll * Gg];
__device__ __align__(256) float g_bi [Ll * Gg];
__device__ __align__(256) float g_wi [Ll * Ee];
__device__ __align__(256) float g_wf [Ll * Ee];
__device__ __align__(256) float g_wo [Ll * Ee];
__device__ __align__(256) float g_sb [Vv];
__device__ __align__(256) float g_xh [Tt * Bb * Gg];
__device__ __align__(256) float g_h0 [Tt * Bb * Ee];
__device__ __align__(256) float g_h1 [Bb * Tt * Ee];

__device__ __forceinline__ float sigf(float x) { return 1.0f / (1.0f + __expf(-x)); }

__device__ __forceinline__ int probe_dt(const void* al) {
    unsigned v = *(const unsigned*)al;
    if (v == 0x3F803F80u) return 1;
    if (v == 0x3C003C00u) return 2;
    return 0;
}
__device__ __forceinline__ float load_as_f32(const void* src, long i, int dt) {
    if (dt == 1) return __bfloat162float(((const __nv_bfloat16*)src)[i]);
    if (dt == 2) return __half2float(((const __half*)src)[i]);
    return ((const float*)src)[i];
}

// ---------------------------------------------------------------------------
// Fused prep (unchanged from R15)
// ---------------------------------------------------------------------------
#define PB_EMB 4000
#define PB_SW  4000
#define PB_WX  128
#define PB_WH  128
#define PB_SMALL 37
#define PB_TOTAL (PB_EMB + PB_SW + PB_WX + PB_WH + PB_SMALL)

__global__ __launch_bounds__(256) void k_prep(
    const void* __restrict__ emb, const void* __restrict__ sw,
    const void* __restrict__ Wx,  const void* __restrict__ Wh,
    const void* __restrict__ al,  const void* __restrict__ b1,
    const void* __restrict__ b2,  const void* __restrict__ bi,
    const void* __restrict__ wi,  const void* __restrict__ wf,
    const void* __restrict__ wo,  const void* __restrict__ sb) {
    const int dt = probe_dt(al);
    int bb = blockIdx.x;
    const int tid = threadIdx.x;
    if (bb < PB_EMB) {
        long base = (long)bb * 1024;
        for (int it = 0; it < 4; it++) {
            long i = base + tid + it * 256;
            g_emb[i] = load_as_f32(emb, i, dt);
        }
        return;
    }
    bb -= PB_EMB;
    if (bb < PB_SW) {
        long base = (long)bb * 1024;
        for (int it = 0; it < 4; it++) {
            long i = base + tid + it * 256;
            float x = load_as_f32(sw, i, dt);
            __nv_bfloat16 h = __float2bfloat16(x);
            g_swH[i] = h;
            g_swL[i] = __float2bfloat16(x - __bfloat162float(h));
        }
        return;
    }
    bb -= PB_SW;
    if (bb < PB_WX) {
        long base = (long)bb * 1024;
        for (int it = 0; it < 4; it++) {
            long i = base + tid + it * 256;
            g_wx[i] = load_as_f32(Wx, i, dt);
        }
        return;
    }
    bb -= PB_WX;
    if (bb < PB_WH) {
        long base = (long)bb * 1024;
        for (int it = 0; it < 4; it++) {
            long i = base + tid + it * 256;
            g_wh[i] = load_as_f32(Wh, i, dt);
        }
        return;
    }
    bb -= PB_WH;
    {
        long e = (long)bb * 1024 + tid;
        for (int it = 0; it < 4; it++, e += 256) {
            if (e < 1024)       g_al[e]        = load_as_f32(al, e, dt);
            else if (e < 2048)  g_b1[e - 1024] = load_as_f32(b1, e - 1024, dt);
            else if (e < 3072)  g_b2[e - 2048] = load_as_f32(b2, e - 2048, dt);
            else if (e < 4096)  g_bi[e - 3072] = load_as_f32(bi, e - 3072, dt);
            else if (e < 4352)  g_wi[e - 4096] = load_as_f32(wi, e - 4096, dt);
            else if (e < 4608)  g_wf[e - 4352] = load_as_f32(wf, e - 4352, dt);
            else if (e < 4864)  g_wo[e - 4608] = load_as_f32(wo, e - 4608, dt);
            else if (e < 36864) g_sb[e - 4864] = load_as_f32(sb, e - 4864, dt);
        }
    }
}

// ---------------------------------------------------------------------------
// XH (unchanged from R15)
// ---------------------------------------------------------------------------
__global__ __launch_bounds__(256) void k_xh(const int* __restrict__ ids,
                                            int mode, int layer) {
    __shared__ float xs[8][Ee];
    const float* Wxl = g_wx + layer * Ee * Gg;
    const int r0 = blockIdx.x * 8;
    const int tid = threadIdx.x;
    for (int idx = tid; idx < 8 * Ee; idx += 256) {
        int rr = idx >> 7, k = idx & 127;
        int r = r0 + rr;
        float v;
        if (mode == 0) {
            int t = r >> 5, b = r & 31;
            int id = ids[b * Tt + t];
            if (id < 0) id = 0;
            if (id >= Vv) id = Vv - 1;
            v = g_emb[(long)id * Ee + k];
        } else {
            v = g_h0[r * Ee + k];
        }
        xs[rr][k] = v;
    }
    __syncthreads();
    const int j = tid;
    float a0[8], a1[8];
#pragma unroll
    for (int rr = 0; rr < 8; rr++) { a0[rr] = 0.f; a1[rr] = 0.f; }
#pragma unroll 4
    for (int k = 0; k < Ee; k++) {
        float w0 = Wxl[k * Gg + j];
        float w1 = Wxl[k * Gg + j + 256];
#pragma unroll
        for (int rr = 0; rr < 8; rr++) {
            float x = xs[rr][k];
            a0[rr] = fmaf(x, w0, a0[rr]);
            a1[rr] = fmaf(x, w1, a1[rr]);
        }
    }
#pragma unroll
    for (int rr = 0; rr < 8; rr++) {
        g_xh[(r0 + rr) * Gg + j]       = a0[rr];
        g_xh[(r0 + rr) * Gg + j + 256] = a1[rr];
    }
}

// ---------------------------------------------------------------------------
// miLSTM v3: 256 threads = 128 col-groups (4 consecutive cols, float4 weights)
// x 2 k-halves (64 k each). 24/64 k-slices register-cached; the rest stream
// as LDG.128 (L1-resident). Halves combined via smem partials.
// ---------------------------------------------------------------------------
#define RK 24
__global__ __launch_bounds__(256) void k_milstm(int layer) {
    __shared__ float hS[Ee];
    __shared__ float gS[Gg];
    __shared__ __align__(16) float4 ps[2][128];
    const int b = blockIdx.x, tid = threadIdx.x;
    const int g = tid & 127, hh = tid >> 7;
    const int c0 = g * 4;
    const int kbase = hh * 64;
    const float4* W4 = reinterpret_cast<const float4*>(g_wh + layer * Ee * Gg);

    float4 al4, b14, b24, bi4;
    float wij = 0.f, wfj = 0.f, woj = 0.f, cc = 0.f;
    if (tid < 128) {
        al4 = *reinterpret_cast<const float4*>(g_al + layer * Gg + c0);
        b14 = *reinterpret_cast<const float4*>(g_b1 + layer * Gg + c0);
        b24 = *reinterpret_cast<const float4*>(g_b2 + layer * Gg + c0);
        bi4 = *reinterpret_cast<const float4*>(g_bi + layer * Gg + c0);
        wij = g_wi[layer * Ee + tid];
        wfj = g_wf[layer * Ee + tid];
        woj = g_wo[layer * Ee + tid];
        hS[tid] = 0.f;
    }
    float4 wr[RK];
#pragma unroll
    for (int k = 0; k < RK; k++) wr[k] = W4[(kbase + k) * 128 + g];
    __syncthreads();
    float* outp = layer ? g_h1 : g_h0;

    for (int t = 0; t < Tt; t++) {
        const float* hp = hS + kbase;
        float4 s = make_float4(0.f, 0.f, 0.f, 0.f);
#pragma unroll
        for (int k = 0; k < RK; k++) {              // register-cached slices
            float hv = hp[k];
            s.x = fmaf(hv, wr[k].x, s.x);
            s.y = fmaf(hv, wr[k].y, s.y);
            s.z = fmaf(hv, wr[k].z, s.z);
            s.w = fmaf(hv, wr[k].w, s.w);
        }
#pragma unroll 8
        for (int k = RK; k < 64; k++) {             // L1-streamed float4
            float hv = hp[k];
            float4 w = W4[(kbase + k) * 128 + g];
            s.x = fmaf(hv, w.x, s.x);
            s.y = fmaf(hv, w.y, s.y);
            s.z = fmaf(hv, w.z, s.z);
            s.w = fmaf(hv, w.w, s.w);
        }
        ps[hh][g] = s;
        __syncthreads();
        if (tid < 128) {                            // combine + gate preact
            float4 sa = ps[0][g], sb = ps[1][g];
            float4 sv = make_float4(sa.x + sb.x, sa.y + sb.y,
                                    sa.z + sb.z, sa.w + sb.w);
            float4 xh4 = *reinterpret_cast<const float4*>(
                g_xh + (t * Bb + b) * Gg + c0);
            float4 g4;
            g4.x = fmaf(al4.x * xh4.x, sv.x, fmaf(b14.x, xh4.x, fmaf(b24.x, sv.x, bi4.x)));
            g4.y = fmaf(al4.y * xh4.y, sv.y, fmaf(b14.y, xh4.y, fmaf(b24.y, sv.y, bi4.y)));
            g4.z = fmaf(al4.z * xh4.z, sv.z, fmaf(b14.z, xh4.z, fmaf(b24.z, sv.z, bi4.z)));
            g4.w = fmaf(al4.w * xh4.w, sv.w, fmaf(b14.w, xh4.w, fmaf(b24.w, sv.w, bi4.w)));
            *reinterpret_cast<float4*>(gS + c0) = g4;
        }
        __syncthreads();
        if (tid < 128) {                            // cell update
            int e = tid;
            float gi = gS[e]           + wij * cc;
            float gj = gS[Ee + e];
            float gf = gS[2 * Ee + e]  + wfj * cc;
            float c_new = sigf(gf + 1.0f) * cc + sigf(gi) * tanhf(gj);
            float go = gS[3 * Ee + e]  + woj * c_new;
            float h_new = sigf(go) * tanhf(c_new);
            cc = c_new;
            hS[e] = h_new;
            if (layer) outp[(b * Tt + t) * Ee + e] = h_new;
            else       outp[(t * Bb + b) * Ee + e] = h_new;
        }
        __syncthreads();
    }
}

// ---------------------------------------------------------------------------
// logits (unchanged from R15): bf16 WMMA, 3-term hi/lo split, 64x64 tiles
// ---------------------------------------------------------------------------
#define LDA 72
#define LDC 68
__global__ __launch_bounds__(256) void k_logits(float* __restrict__ out,
                                                long nout) {
    __shared__ __align__(32) char smem_raw[4 * 64 * LDA * 2];
    __nv_bfloat16* Ah = reinterpret_cast<__nv_bfloat16*>(smem_raw);
    __nv_bfloat16* Al = Ah + 64 * LDA;
    __nv_bfloat16* Bh = Al + 64 * LDA;
    __nv_bfloat16* Bl = Bh + 64 * LDA;
    const int n0 = blockIdx.x * 64, m0 = blockIdx.y * 64;
    const int tid = threadIdx.x;
    const int w = tid >> 5;
    const int wm = (w & 1) * 32;
    const int wn = (w >> 1) * 16;

    wm::fragment<wm::accumulator, 16, 16, 16, float> cf[2];
#pragma unroll
    for (int i = 0; i < 2; i++) wm::fill_fragment(cf[i], 0.f);

#pragma unroll
    for (int kc = 0; kc < Ee; kc += 64) {
#pragma unroll
        for (int it = 0; it < 16; it++) {
            int idx = tid + it * 256;
            int r = idx >> 6, k = idx & 63;
            float x = g_h1[(long)(m0 + r) * Ee + kc + k];
            __nv_bfloat16 h = __float2bfloat16(x);
            Ah[r * LDA + k] = h;
            Al[r * LDA + k] = __float2bfloat16(x - __bfloat162float(h));
        }
#pragma unroll
        for (int it = 0; it < 8; it++) {
            int idx = tid + it * 256;
            int r = idx >> 5, c2 = idx & 31;
            long src = (long)(n0 + r) * 64 + (kc >> 1) + c2;
            unsigned vh = reinterpret_cast<const unsigned*>(g_swH)[src];
            unsigned vl = reinterpret_cast<const unsigned*>(g_swL)[src];
            reinterpret_cast<unsigned*>(Bh + r * LDA)[c2] = vh;
            reinterpret_cast<unsigned*>(Bl + r * LDA)[c2] = vl;
        }
        __syncthreads();

#pragma unroll
        for (int kf = 0; kf < 4; kf++) {
            wm::fragment<wm::matrix_b, 16, 16, 16, __nv_bfloat16, wm::col_major> bh, bl;
            wm::load_matrix_sync(bh, Bh + wn * LDA + kf * 16, LDA);
            wm::load_matrix_sync(bl, Bl + wn * LDA + kf * 16, LDA);
#pragma unroll
            for (int i = 0; i < 2; i++) {
                wm::fragment<wm::matrix_a, 16, 16, 16, __nv_bfloat16, wm::row_major> ah, alo;
                wm::load_matrix_sync(ah,  Ah + (wm + i * 16) * LDA + kf * 16, LDA);
                wm::load_matrix_sync(alo, Al + (wm + i * 16) * LDA + kf * 16, LDA);
                wm::mma_sync(cf[i], ah,  bh, cf[i]);
                wm::mma_sync(cf[i], ah,  bl, cf[i]);
                wm::mma_sync(cf[i], alo, bh, cf[i]);
            }
        }
        __syncthreads();
    }

    float* Cs = reinterpret_cast<float*>(smem_raw);
#pragma unroll
    for (int i = 0; i < 2; i++)
        wm::store_matrix_sync(Cs + (wm + i * 16) * LDC + wn, cf[i], LDC,
                              wm::mem_row_major);
    __syncthreads();
#pragma unroll
    for (int it = 0; it < 16; it++) {
        int idx = tid + it * 256;
        int r = idx >> 6, c = idx & 63;
        long o = (long)(m0 + r) * Vv + n0 + c;
        if (o < nout) out[o] = Cs[r * LDC + c] + g_sb[n0 + c];
    }
}

// ---------------------------------------------------------------------------
extern "C" void kernel_launch(void* const* d_in, const int* in_sizes, int n_in,
                              void* d_out, int out_size) {
    long nout = (long)out_size;

    static const int sigE[13]  = {4096, 4096000, 131072, 131072, 1024, 1024,
                                  1024, 1024, 256, 256, 256, 4096000, 32000};
    static const int alphE[13] = {131072, 131072, 1024, 1024, 1024, 1024,
                                  4096000, 4096, 32000, 4096000, 256, 256, 256};
    int m_sigE = (n_in == 13), m_alphE = (n_in == 13);
    int m_sigB = (n_in == 13), m_alphB = (n_in == 13);
    for (int i = 0; i < 13 && i < n_in; i++) {
        if (in_sizes[i] != sigE[i])      m_sigE = 0;
        if (in_sizes[i] != alphE[i])     m_alphE = 0;
        if (in_sizes[i] != 4 * sigE[i])  m_sigB = 0;
        if (in_sizes[i] != 4 * alphE[i]) m_alphB = 0;
    }

    const void *ids = 0, *emb = 0, *Wx = 0, *Wh = 0, *al = 0, *b1 = 0, *b2 = 0,
               *bi = 0, *wi = 0, *wf = 0, *wo = 0, *sw = 0, *sb = 0;
    if (m_sigE || m_sigB) {
        ids = d_in[0]; emb = d_in[1]; Wx = d_in[2]; Wh = d_in[3];
        al = d_in[4]; b1 = d_in[5]; b2 = d_in[6]; bi = d_in[7];
        wi = d_in[8]; wf = d_in[9]; wo = d_in[10]; sw = d_in[11]; sb = d_in[12];
    } else if (m_alphE || m_alphB) {
        Wh = d_in[0]; Wx = d_in[1]; al = d_in[2]; b1 = d_in[3]; b2 = d_in[4];
        bi = d_in[5]; emb = d_in[6]; ids = d_in[7]; sb = d_in[8]; sw = d_in[9];
        wf = d_in[10]; wi = d_in[11]; wo = d_in[12];
    } else if (n_in >= 13) {
        int maxs = 0;
        for (int i = 0; i < n_in; i++) if (in_sizes[i] > maxs) maxs = in_sizes[i];
        int cnt4 = -1, cnt3 = -1;
        for (int i = 0; i < n_in; i++) {
            int c = 0;
            for (int k2 = 0; k2 < n_in; k2++) if (in_sizes[k2] == in_sizes[i]) c++;
            if (c == 4) cnt4 = in_sizes[i];
            if (c == 3) cnt3 = in_sizes[i];
        }
        int nG = 0, nP = 0, nBig = 0, nMid = 0;
        int mid = -1;
        for (int i = 0; i < n_in; i++) {
            int s = in_sizes[i];
            if (s == maxs || s == cnt4 || s == cnt3) continue;
            int c = 0;
            for (int k2 = 0; k2 < n_in; k2++) if (in_sizes[k2] == s) c++;
            if (c == 2) mid = s;
        }
        const void* singles[2] = {0, 0}; int ssz[2] = {0, 0}; int nS = 0;
        for (int i = 0; i < n_in; i++) {
            int s = in_sizes[i]; const void* p = d_in[i];
            if (s == maxs)      { if (nBig++ == 0) emb = p; else sw = p; }
            else if (s == mid)  { if (nMid++ == 0) Wx = p; else Wh = p; }
            else if (s == cnt4) { if (nG == 0) al = p; else if (nG == 1) b1 = p;
                                  else if (nG == 2) b2 = p; else bi = p; nG++; }
            else if (s == cnt3) { if (nP == 0) wi = p; else if (nP == 1) wf = p;
                                  else wo = p; nP++; }
            else if (nS < 2)    { singles[nS] = p; ssz[nS] = s; nS++; }
        }
        if (nS == 2) {
            if (ssz[0] < ssz[1]) { ids = singles[0]; sb = singles[1]; }
            else                 { ids = singles[1]; sb = singles[0]; }
        }
    }
    if (!ids || !emb || !sw || !Wx || !Wh || !al || !b1 || !b2 || !bi ||
        !wi || !wf || !wo || !sb) return;

    k_prep<<<PB_TOTAL, 256>>>(emb, sw, Wx, Wh, al, b1, b2, bi, wi, wf, wo, sb);

    k_xh<<<(Tt * Bb) / 8, 256>>>((const int*)ids, 0, 0);
    k_milstm<<<Bb, 256>>>(0);
    k_xh<<<(Tt * Bb) / 8, 256>>>((const int*)ids, 1, 1);
    k_milstm<<<Bb, 256>>>(1);

    dim3 grid(Vv / 64, (Bb * Tt) / 64);
    k_logits<<<grid, 256>>>((float*)d_out, nout);
}